// round 1
// baseline (speedup 1.0000x reference)
#include <cuda_runtime.h>
#include <cuda_bf16.h>
#include <math.h>

// Problem constants (fixed shapes from reference)
#define QN    16          // Qi == Qo == 16
#define C0N   8
#define C1N   4
#define DIMC  20          // C0 + 3*C1
#define K3T   125         // 5^3 taps
#define NCH   320         // DIMC * QN  (both in and out flattened channels)
#define VOX   512         // 8^3 voxels
#define GK    8           // gaussian basis
#define NSPLIT 20         // split-K over input channels (16 ci each)

// Scratch (static device globals — allocation-free per harness rules)
__device__ float g_kern[NCH * NCH * K3T];     // [ci][och][tap]  (51.2 MB)
__device__ float g_part[NSPLIT * NCH * VOX];  // [split][och][vox] (13.1 MB)

// ---------------------------------------------------------------------------
// Kernel 1: build the equivariant conv kernel.
// one thread per (p, q, tap); writes the 20x20 channel block for that tap.
// ---------------------------------------------------------------------------
__global__ void build_kern_kernel(const float* __restrict__ q_in,
                                  const float* __restrict__ q_out,
                                  const float* __restrict__ w_ss,
                                  const float* __restrict__ w_vs,
                                  const float* __restrict__ w_sv,
                                  const float* __restrict__ w_vv0,
                                  const float* __restrict__ w_vv1) {
    int idx = blockIdx.x * blockDim.x + threadIdx.x;
    if (idx >= QN * QN * K3T) return;
    int t = idx % K3T;
    int q = (idx / K3T) % QN;
    int p = idx / (K3T * QN);

    int dz = t / 25, dy = (t / 5) % 5, dx = t % 5;
    // v = p_off - (q_out[p] - q_in[q]);  p_off components (z,y,x)
    float v0 = (float)(dz - 2) - (q_out[p * 3 + 0] - q_in[q * 3 + 0]);
    float v1 = (float)(dy - 2) - (q_out[p * 3 + 1] - q_in[q * 3 + 1]);
    float v2 = (float)(dx - 2) - (q_out[p * 3 + 2] - q_in[q * 3 + 2]);
    float r  = sqrtf(v0 * v0 + v1 * v1 + v2 * v2);
    float inv = (r > 1e-6f) ? (1.0f / r) : 0.0f;  // where(r>eps, v/max(r,eps), 0)
    float u[3] = {v0 * inv, v1 * inv, v2 * inv};

    const float sigma = 5.5f / 7.0f;              // R_MAX/(G-1); centers = g*sigma
    float R[GK];
#pragma unroll
    for (int g = 0; g < GK; g++) {
        float d = (r - sigma * (float)g) / sigma;
        R[g] = expf(-0.5f * d * d);
    }

    // cross[i][j] = sum_m eps[i][m][j] * u[m]
    float cross[3][3];
    cross[0][0] = 0.f;    cross[0][1] = -u[2];  cross[0][2] =  u[1];
    cross[1][0] =  u[2];  cross[1][1] = 0.f;    cross[1][2] = -u[0];
    cross[2][0] = -u[1];  cross[2][1] =  u[0];  cross[2][2] = 0.f;

    // g_kern[ci][och][tap], ci = col*QN + q, och = row*QN + p
#define KSTORE(row, col, val) \
    g_kern[((size_t)(((col) * QN + q)) * NCH + ((row) * QN + p)) * K3T + t] = (val)

    // (0,0,0): scalar->scalar
    for (int a = 0; a < C0N; a++)
        for (int c = 0; c < C0N; c++) {
            float s = 0.f;
#pragma unroll
            for (int g = 0; g < GK; g++) s += w_ss[(a * C0N + c) * GK + g] * R[g];
            KSTORE(a, c, s);
        }
    // (1,0,1): vector-in -> scalar-out  (K_sv): col = 8 + c*3 + j
    for (int a = 0; a < C0N; a++)
        for (int c = 0; c < C1N; c++) {
            float s = 0.f;
#pragma unroll
            for (int g = 0; g < GK; g++) s += w_sv[(a * C1N + c) * GK + g] * R[g];
#pragma unroll
            for (int j = 0; j < 3; j++) KSTORE(a, 8 + c * 3 + j, s * u[j]);
        }
    // (0,1,1): scalar-in -> vector-out (K_vs): row = 8 + a*3 + m
    for (int a = 0; a < C1N; a++)
        for (int c = 0; c < C0N; c++) {
            float s = 0.f;
#pragma unroll
            for (int g = 0; g < GK; g++) s += w_vs[(a * C0N + c) * GK + g] * R[g];
#pragma unroll
            for (int m = 0; m < 3; m++) KSTORE(8 + a * 3 + m, c, s * u[m]);
        }
    // (1,1,0) + (1,1,1): vector->vector
    for (int a = 0; a < C1N; a++)
        for (int c = 0; c < C1N; c++) {
            float d0 = 0.f, d1 = 0.f;
#pragma unroll
            for (int g = 0; g < GK; g++) {
                d0 += w_vv0[(a * C1N + c) * GK + g] * R[g];
                d1 += w_vv1[(a * C1N + c) * GK + g] * R[g];
            }
#pragma unroll
            for (int i = 0; i < 3; i++)
#pragma unroll
                for (int j = 0; j < 3; j++) {
                    float val = ((i == j) ? d0 : 0.f)
                              + 0.7071067811865476f * d1 * cross[i][j];
                    KSTORE(8 + a * 3 + i, 8 + c * 3 + j, val);
                }
        }
#undef KSTORE
}

// ---------------------------------------------------------------------------
// Kernel 2: split-K implicit GEMM (fp32 SIMT).
// grid = (10 och-tiles of 32, NSPLIT ci-splits of 16). block = 256 threads.
// thread tile: 8 och x 8 vox (one x-row of the 8^3 volume).
// smem x is padded with stride_y=13, stride_z=168 for conflict-free LDS.
// ---------------------------------------------------------------------------
#define SY 13
#define SZ 168

__global__ void __launch_bounds__(256, 2)
gemm_kernel(const float* __restrict__ x) {
    __shared__ float xp[12 * SZ];        // padded 12x12x12 volume (2016 floats)
    __shared__ float ks_s[K3T * 32];     // kern tile: [tap][och_sub]

    const int tid   = threadIdx.x;
    const int och0  = blockIdx.x * 32;
    const int ksp   = blockIdx.y;        // 0..NSPLIT-1
    const int o_sub = tid >> 6;          // 0..3  -> my 8 och start at o_sub*8
    const int v_sub = tid & 63;          // 0..63 -> (z, y) row of 8 voxels
    const int z = v_sub >> 3, y = v_sub & 7;

    float acc[8][8];
#pragma unroll
    for (int o = 0; o < 8; o++)
#pragma unroll
        for (int i = 0; i < 8; i++) acc[o][i] = 0.f;

    // zero padded volume once (padding stays zero; interior rewritten each ci)
    for (int i = tid; i < 12 * SZ; i += 256) xp[i] = 0.f;

    for (int ci_it = 0; ci_it < 16; ++ci_it) {
        const int ci = ksp * 16 + ci_it;
        __syncthreads();
        // fill interior: voxel (zz,yy,xx) -> padded (zz+2, yy+2, xx+2)
        for (int i = tid; i < VOX; i += 256) {
            int zz = i >> 6, yy = (i >> 3) & 7, xx = i & 7;
            xp[(zz + 2) * SZ + (yy + 2) * SY + (xx + 2)] = x[ci * VOX + i];
        }
        // load kern tile: 32 och x 125 taps
        for (int i = tid; i < 32 * K3T; i += 256) {
            int o = i / K3T, t = i - o * K3T;
            ks_s[t * 32 + o] = g_kern[((size_t)ci * NCH + (och0 + o)) * K3T + t];
        }
        __syncthreads();

        const int base0 = z * SZ + y * SY;
        for (int dz = 0; dz < 5; dz++) {
            for (int dy = 0; dy < 5; dy++) {
                const float* xrow = &xp[base0 + dz * SZ + dy * SY];
                const float* kp0  = &ks_s[((dz * 5 + dy) * 5) * 32 + o_sub * 8];
#pragma unroll
                for (int dx = 0; dx < 5; dx++) {
                    float xv[8];
#pragma unroll
                    for (int i = 0; i < 8; i++) xv[i] = xrow[dx + i];
                    const float* kp = kp0 + dx * 32;
#pragma unroll
                    for (int o = 0; o < 8; o++) {
                        float kv = kp[o];
#pragma unroll
                        for (int i = 0; i < 8; i++) acc[o][i] += kv * xv[i];
                    }
                }
            }
        }
    }

    // write partials: g_part[ksp][och][vox]
    const int vbase = v_sub << 3;
#pragma unroll
    for (int o = 0; o < 8; o++) {
        int och = och0 + o_sub * 8 + o;
        float* dst = &g_part[((size_t)ksp * NCH + och) * VOX + vbase];
#pragma unroll
        for (int i = 0; i < 8; i++) dst[i] = acc[o][i];
    }
}

// ---------------------------------------------------------------------------
// Kernel 3: reduce split-K partials + bias (deterministic order).
// ---------------------------------------------------------------------------
__global__ void reduce_kernel(float* __restrict__ out,
                              const float* __restrict__ bias) {
    int i = blockIdx.x * blockDim.x + threadIdx.x;
    if (i >= NCH * VOX) return;
    int och = i >> 9;          // /512
    int r   = och >> 4;        // /16 -> dim_out index 0..19
    float s = (r < C0N) ? bias[r] : 0.f;
#pragma unroll
    for (int k = 0; k < NSPLIT; k++) s += g_part[(size_t)k * NCH * VOX + i];
    out[i] = s;
}

// ---------------------------------------------------------------------------
extern "C" void kernel_launch(void* const* d_in, const int* in_sizes, int n_in,
                              void* d_out, int out_size) {
    const float* x     = (const float*)d_in[0];
    const float* q_in  = (const float*)d_in[1];
    const float* q_out = (const float*)d_in[2];
    const float* w_ss  = (const float*)d_in[3];
    const float* w_vs  = (const float*)d_in[4];
    const float* w_sv  = (const float*)d_in[5];
    const float* w_vv0 = (const float*)d_in[6];
    const float* w_vv1 = (const float*)d_in[7];
    const float* bias  = (const float*)d_in[8];
    float* out = (float*)d_out;

    build_kern_kernel<<<(QN * QN * K3T + 255) / 256, 256>>>(
        q_in, q_out, w_ss, w_vs, w_sv, w_vv0, w_vv1);

    dim3 grid(NCH / 32, NSPLIT);
    gemm_kernel<<<grid, 256>>>(x);

    reduce_kernel<<<(NCH * VOX + 255) / 256, 256>>>(out, bias);
}